// round 15
// baseline (speedup 1.0000x reference)
#include <cuda_runtime.h>
#include <math.h>

// Block layout (R9 ordering — measured best): small-work blocks FIRST so they
// overlap under wave 1 of the streaming blocks.
#define N_GLOBAL_BLK  1
#define N_PHRASE_BLK  64
#define N_MUS_BLK     32
#define N_ADV_BLK     16
#define N_SMALL_BLK   (N_GLOBAL_BLK + N_PHRASE_BLK + N_MUS_BLK + N_ADV_BLK)   // 113
#define N_STREAM_BLK  512
#define N_BLOCKS      (N_SMALL_BLK + N_STREAM_BLK)                            // 625

// Shared scratch: worst case fm_split_body<4,8> (RPB=2):
// smr[2*512] + smf[2*512] + red[8] = 2056 floats. Pad.
#define SM_FLOATS (2 * 2 * 512 + 16)

__device__ float g_part[N_BLOCKS];
__device__ unsigned int g_done = 0;   // last block resets to 0 -> graph-replay safe

__device__ __forceinline__ float warp_sum(float v) {
    #pragma unroll
    for (int o = 16; o; o >>= 1) v += __shfl_xor_sync(0xffffffffu, v, o);
    return v;
}

// ---------------------------------------------------------------------------
// Streaming feature-matching body: warp owns one full 512-ch row.
// ---------------------------------------------------------------------------
__device__ __forceinline__ float fm_row_warp(
    const float* __restrict__ real, const float* __restrict__ fake,
    int s, int B, int S, float scale, int lane)
{
    const float4* pr = (const float4*)real + (size_t)s * 128 + lane;
    const float4* pf = (const float4*)fake + (size_t)s * 128 + lane;
    const size_t bstride = (size_t)S * 128;

    float ar[16], af[16];
    #pragma unroll
    for (int i = 0; i < 16; ++i) { ar[i] = 0.0f; af[i] = 0.0f; }

    #pragma unroll 2
    for (int b = 0; b < B; ++b) {
        float4 r[4], f[4];
        #pragma unroll
        for (int k = 0; k < 4; ++k) {
            r[k] = pr[(size_t)b * bstride + k * 32];
            f[k] = pf[(size_t)b * bstride + k * 32];
        }
        float sr = 0.0f, sf = 0.0f;
        #pragma unroll
        for (int k = 0; k < 4; ++k) {
            sr += r[k].x * r[k].x + r[k].y * r[k].y + r[k].z * r[k].z + r[k].w * r[k].w;
            sf += f[k].x * f[k].x + f[k].y * f[k].y + f[k].z * f[k].z + f[k].w * f[k].w;
        }
        sr = warp_sum(sr);
        sf = warp_sum(sf);
        const float ir = 1.0f / fmaxf(sqrtf(sr), 1e-12f);
        const float jf = 1.0f / fmaxf(sqrtf(sf), 1e-12f);
        #pragma unroll
        for (int k = 0; k < 4; ++k) {
            ar[4*k+0] += r[k].x * ir;  af[4*k+0] += f[k].x * jf;
            ar[4*k+1] += r[k].y * ir;  af[4*k+1] += f[k].y * jf;
            ar[4*k+2] += r[k].z * ir;  af[4*k+2] += f[k].z * jf;
            ar[4*k+3] += r[k].w * ir;  af[4*k+3] += f[k].w * jf;
        }
    }

    const float invB = 1.0f / (float)B;
    float v = 0.0f;
    #pragma unroll
    for (int i = 0; i < 16; ++i) {
        float d = (af[i] - ar[i]) * invB;
        v += d * d;
    }
    return warp_sum(v) * scale;
}

// ---------------------------------------------------------------------------
// Batch-split body for small-row tensors: WPR warps per row; partial
// normalized accumulators combined in smem. Writes block partial to g_part.
// ---------------------------------------------------------------------------
template<int WPR, int NW>
__device__ __forceinline__ void fm_split_body(
    float* sm,
    const float* __restrict__ real, const float* __restrict__ fake,
    int B, int S, float scale, int row_blk)
{
    constexpr int RPB = NW / WPR;
    float* smr = sm;                     // [RPB][512]
    float* smf = sm + RPB * 512;         // [RPB][512]
    float* red = sm + 2 * RPB * 512;     // [NW]

    const int wid  = threadIdx.x >> 5;
    const int lane = threadIdx.x & 31;
    const int rloc = wid / WPR;
    const int wsub = wid % WPR;
    const int s    = row_blk * RPB + rloc;

    for (int i = threadIdx.x; i < RPB * 512; i += NW * 32) {
        smr[i] = 0.0f;
        smf[i] = 0.0f;
    }
    __syncthreads();

    if (s < S) {
        const float4* pr = (const float4*)real + (size_t)s * 128 + lane;
        const float4* pf = (const float4*)fake + (size_t)s * 128 + lane;
        const size_t bstride = (size_t)S * 128;
        const int bpw = B / WPR;
        const int b0  = wsub * bpw;

        float ar[16], af[16];
        #pragma unroll
        for (int i = 0; i < 16; ++i) { ar[i] = 0.0f; af[i] = 0.0f; }

        #pragma unroll 2
        for (int b = b0; b < b0 + bpw; ++b) {
            float4 r[4], f[4];
            #pragma unroll
            for (int k = 0; k < 4; ++k) {
                r[k] = pr[(size_t)b * bstride + k * 32];
                f[k] = pf[(size_t)b * bstride + k * 32];
            }
            float sr = 0.0f, sf = 0.0f;
            #pragma unroll
            for (int k = 0; k < 4; ++k) {
                sr += r[k].x * r[k].x + r[k].y * r[k].y + r[k].z * r[k].z + r[k].w * r[k].w;
                sf += f[k].x * f[k].x + f[k].y * f[k].y + f[k].z * f[k].z + f[k].w * f[k].w;
            }
            sr = warp_sum(sr);
            sf = warp_sum(sf);
            const float ir = 1.0f / fmaxf(sqrtf(sr), 1e-12f);
            const float jf = 1.0f / fmaxf(sqrtf(sf), 1e-12f);
            #pragma unroll
            for (int k = 0; k < 4; ++k) {
                ar[4*k+0] += r[k].x * ir;  af[4*k+0] += f[k].x * jf;
                ar[4*k+1] += r[k].y * ir;  af[4*k+1] += f[k].y * jf;
                ar[4*k+2] += r[k].z * ir;  af[4*k+2] += f[k].z * jf;
                ar[4*k+3] += r[k].w * ir;  af[4*k+3] += f[k].w * jf;
            }
        }
        #pragma unroll
        for (int k = 0; k < 4; ++k) {
            const int ch = rloc * 512 + (lane + 32 * k) * 4;
            atomicAdd(&smr[ch+0], ar[4*k+0]);
            atomicAdd(&smr[ch+1], ar[4*k+1]);
            atomicAdd(&smr[ch+2], ar[4*k+2]);
            atomicAdd(&smr[ch+3], ar[4*k+3]);
            atomicAdd(&smf[ch+0], af[4*k+0]);
            atomicAdd(&smf[ch+1], af[4*k+1]);
            atomicAdd(&smf[ch+2], af[4*k+2]);
            atomicAdd(&smf[ch+3], af[4*k+3]);
        }
    }
    __syncthreads();

    const float invB = 1.0f / (float)B;
    float v = 0.0f;
    for (int i = threadIdx.x; i < RPB * 512; i += NW * 32) {
        const int rr = i >> 9;
        if (row_blk * RPB + rr < S) {
            float d = (smf[i] - smr[i]) * invB;
            v += d * d;
        }
    }
    v = warp_sum(v);
    if (lane == 0) red[wid] = v;
    __syncthreads();
    if (threadIdx.x == 0) {
        float t = 0.0f;
        #pragma unroll
        for (int i = 0; i < NW; ++i) t += red[i];
        g_part[blockIdx.x] = t * scale;
    }
}

// ---------------------------------------------------------------------------
// Mega kernel (R9 block order) with fused last-block finalize.
//   [0, 1)      : global feature
//   [1, 65)     : phrase feature (2 rows/block)
//   [65, 97)    : musical perceptual (tokens)
//   [97, 113)   : adversarial BCE x3
//   [113, 625)  : local+input streaming (8 rows/blk)
// Release fence is issued by thread 0 ONLY (it is the sole writer of
// g_part[blockIdx.x] and the sole atomic incrementer) — the R14 version
// fenced with all 256 threads and that cost ~7us of stream bandwidth.
// ---------------------------------------------------------------------------
__global__ void __launch_bounds__(256, 2) mega_k(
    const float* __restrict__ real_local,  const float* __restrict__ fake_local,
    const float* __restrict__ real_phrase, const float* __restrict__ fake_phrase,
    const float* __restrict__ real_global, const float* __restrict__ fake_global,
    const float* __restrict__ real_input,  const float* __restrict__ fake_input,
    const float* __restrict__ local_logits, const float* __restrict__ phrase_logits,
    const float* __restrict__ global_logits, const int* __restrict__ tokens,
    int B, int S, int P, float* __restrict__ out, int out_n)
{
    __shared__ float sm_big[SM_FLOATS];
    __shared__ bool  sm_last;

    const int blk  = blockIdx.x;
    const int lane = threadIdx.x & 31;
    const int wid  = threadIdx.x >> 5;
    const int D = 512;

    if (blk < N_GLOBAL_BLK) {
        // global feature: 1 row, 8 warps (4 batches each)
        fm_split_body<8, 8>(sm_big, real_global, fake_global, B, 1,
                            0.2f / (4.0f * D), 0);
    } else if (blk < N_GLOBAL_BLK + N_PHRASE_BLK) {
        // phrase: 4 warps/row, 2 rows/block
        fm_split_body<4, 8>(sm_big, real_phrase, fake_phrase, B, P,
                            0.4f / (4.0f * P * D), blk - N_GLOBAL_BLK);
    } else if (blk < N_GLOBAL_BLK + N_PHRASE_BLK + N_MUS_BLK) {
        // musical perceptual over tokens
        const int mblk = blk - N_GLOBAL_BLK - N_PHRASE_BLK;
        const int n = B * (S - 1);
        const float c_rm = 1.0f / (float)(B * (S - 1));
        const float c_h  = 1.0f / (float)(B * S);
        float sum = 0.0f;
        for (int idx = mblk * 256 + threadIdx.x; idx < n; idx += N_MUS_BLK * 256) {
            int b = idx / (S - 1);
            int i = idx - b * (S - 1);
            int t0 = tokens[b * S + i];
            int t1 = tokens[b * S + i + 1];
            int ts0 = (t0 >= 256 && t0 < 768) ? 1 : 0;
            int ts1 = (t1 >= 256 && t1 < 768) ? 1 : 0;
            int p0 = (t0 < 128) ? t0 : 0;
            int p1 = (t1 < 128) ? t1 : 0;
            int iv = abs(p0 % 12 - p1 % 12);
            float r = (ts0 != ts1) ? 1.0f : 0.0f;
            float h = (iv == 6 || iv == 11) ? 1.0f : 0.0f;
            float m = (abs(p1 - p0) > 12) ? 1.0f : 0.0f;
            sum += r * c_rm + h * c_h + m * c_rm;
        }
        sum = warp_sum(sum);
        if (lane == 0) sm_big[wid] = sum;
        __syncthreads();
        if (threadIdx.x == 0) {
            float t = 0.0f;
            #pragma unroll
            for (int i = 0; i < 8; ++i) t += sm_big[i];
            g_part[blockIdx.x] = t;
        }
    } else if (blk < N_SMALL_BLK) {
        // adversarial: three BCE terms over concatenated index space
        const int ablk = blk - N_GLOBAL_BLK - N_PHRASE_BLK - N_MUS_BLK;
        const int n0 = B * S, n1 = B * P, n2 = B;
        const float c0 = 0.4f / (float)n0;
        const float c1 = 0.4f / (float)n1;
        const float c2 = 0.2f / (float)n2;
        const int n = n0 + n1 + n2;
        float sum = 0.0f;
        for (int idx = ablk * 256 + threadIdx.x; idx < n; idx += N_ADV_BLK * 256) {
            float v, c;
            if (idx < n0)           { v = local_logits[idx];             c = c0; }
            else if (idx < n0 + n1) { v = phrase_logits[idx - n0];       c = c1; }
            else                    { v = global_logits[idx - n0 - n1];  c = c2; }
            sum += c * (fmaxf(-v, 0.0f) + log1pf(expf(-fabsf(v))));
        }
        sum = warp_sum(sum);
        if (lane == 0) sm_big[wid] = sum;
        __syncthreads();
        if (threadIdx.x == 0) {
            float t = 0.0f;
            #pragma unroll
            for (int i = 0; i < 8; ++i) t += sm_big[i];
            g_part[blockIdx.x] = t;
        }
    } else {
        // streaming local + input: gwarp in [0, 2S)
        const int gwarp = (blk - N_SMALL_BLK) * 8 + wid;
        float v;
        if (gwarp < S) {
            v = fm_row_warp(real_local, fake_local, gwarp, B, S,
                            0.4f / (4.0f * S * D), lane);
        } else {
            v = fm_row_warp(real_input, fake_input, gwarp - S, B, S,
                            0.1f / (4.0f * S * D), lane);
        }
        if (lane == 0) sm_big[wid] = v;
        __syncthreads();
        if (threadIdx.x == 0) {
            float t = 0.0f;
            #pragma unroll
            for (int i = 0; i < 8; ++i) t += sm_big[i];
            g_part[blockIdx.x] = t;
        }
    }

    // ---- fused finalize: last block to finish reduces all partials ----
    // Release fence by thread 0 only (sole writer of g_part[blk] + sole
    // atomic incrementer). All other threads pass straight through.
    if (threadIdx.x == 0) {
        __threadfence();
        unsigned int t = atomicAdd(&g_done, 1u);
        sm_last = (t == (unsigned)(N_BLOCKS - 1));
    }
    __syncthreads();

    if (sm_last) {
        __threadfence();   // acquire side: order g_part reads after the atomic
        float sum = 0.0f;
        for (int i = threadIdx.x; i < N_BLOCKS; i += 256) sum += g_part[i];
        sum = warp_sum(sum);
        if (lane == 0) sm_big[wid] = sum;
        __syncthreads();
        if (threadIdx.x == 0) {
            float t = 0.0f;
            #pragma unroll
            for (int i = 0; i < 8; ++i) t += sm_big[i];
            sm_big[0] = t;
            g_done = 0;   // reset for next graph replay (only this block alive)
        }
        __syncthreads();
        const float v = sm_big[0];
        for (int i = threadIdx.x; i < out_n; i += 256) out[i] = v;
    }
}

extern "C" void kernel_launch(void* const* d_in, const int* in_sizes, int n_in,
                              void* d_out, int out_size)
{
    const float* real_local    = (const float*)d_in[0];
    const float* real_phrase   = (const float*)d_in[1];
    const float* real_global   = (const float*)d_in[2];
    const float* real_input    = (const float*)d_in[3];
    const float* fake_local    = (const float*)d_in[4];
    const float* fake_phrase   = (const float*)d_in[5];
    const float* fake_global   = (const float*)d_in[6];
    const float* fake_input    = (const float*)d_in[7];
    const float* local_logits  = (const float*)d_in[8];
    const float* phrase_logits = (const float*)d_in[9];
    const float* global_logits = (const float*)d_in[10];
    const int*   tokens        = (const int*)d_in[11];

    const int B = 32, S = 2048, P = 128;

    mega_k<<<N_BLOCKS, 256>>>(
        real_local, fake_local,
        real_phrase, fake_phrase,
        real_global, fake_global,
        real_input, fake_input,
        local_logits, phrase_logits, global_logits, tokens,
        B, S, P, (float*)d_out, out_size);
}